// round 8
// baseline (speedup 1.0000x reference)
#include <cuda_runtime.h>
#include <cuda_bf16.h>
#include <cstdint>

// ---------------- problem constants ----------------
#define NUM_CHARS 128
#define UNITS     256
#define BATCH     512
#define SEQ       1024

// ---------------- decomposition ----------------
#define GROUPS 16      // batch groups (= clusters)
#define CPG    8       // CTAs per group (cluster size)
#define MBATCH 32      // batch rows per group
#define UC     32      // units per CTA
#define KDIM   256     // h dimension (MMA K)
#define NCTAS  (GROUPS*CPG)
#define NTHREADS 512   // 16 warps: 4 m-groups x 4 n-quarters

// ---------------- smem layout (byte offsets) ----------------
#define OFF_AHI    1024                     // W_hi slice [128 m][256 k] bf16 swizzled = 64KB
#define OFF_ALO    (OFF_AHI + 65536)        // W_lo slice                              = 64KB
#define OFF_BHI    (OFF_ALO + 65536)        // h_hi tile [32 n][256 k] bf16 swizzled   = 16KB
#define OFF_BLO    (OFF_BHI + 16384)        // h_lo tile                               = 16KB
#define OFF_WX     (OFF_BLO + 16384)        // Wx slice fp32 [128 m][130 ch]           = 66560B
#define SMEM_TOTAL (OFF_WX + 66560)

// ---------------- global scratch ----------------
__device__ unsigned g_h[2][BATCH * UNITS];   // packed (bf16 hi | bf16 lo << 16), double-buffered

// ---------------- helpers ----------------
__device__ __forceinline__ uint32_t smem_u32(const void* p) {
    uint32_t a;
    asm("{ .reg .u64 t; cvta.to.shared.u64 t, %1; cvt.u32.u64 %0, t; }" : "=r"(a) : "l"(p));
    return a;
}
#define CLUSTER_ARRIVE() asm volatile("barrier.cluster.arrive.aligned;" ::: "memory")
#define CLUSTER_WAIT()   asm volatile("barrier.cluster.wait.aligned;" ::: "memory")

// row-major tile, 512B row stride, 16B chunks XOR-swizzled by row%8 (conflict-free ldmatrix)
__device__ __forceinline__ uint32_t swz(int row, int k) {
    return (uint32_t)row * 512u
         + (((((uint32_t)k >> 3) << 4)) ^ (((uint32_t)row & 7u) << 4))
         + (((uint32_t)k & 7u) << 1);
}

__device__ __forceinline__ void ldsm_x4(uint32_t r[4], uint32_t addr) {
    asm volatile("ldmatrix.sync.aligned.m8n8.x4.shared.b16 {%0,%1,%2,%3}, [%4];"
                 : "=r"(r[0]), "=r"(r[1]), "=r"(r[2]), "=r"(r[3]) : "r"(addr));
}
__device__ __forceinline__ void ldsm_x2(uint32_t r[2], uint32_t addr) {
    asm volatile("ldmatrix.sync.aligned.m8n8.x2.shared.b16 {%0,%1}, [%2];"
                 : "=r"(r[0]), "=r"(r[1]) : "r"(addr));
}

__device__ __forceinline__ void mma_bf16(float c[4],
                                         uint32_t a0, uint32_t a1, uint32_t a2, uint32_t a3,
                                         uint32_t b0, uint32_t b1) {
    asm volatile("mma.sync.aligned.m16n8k16.row.col.f32.bf16.bf16.f32 "
                 "{%0,%1,%2,%3}, {%4,%5,%6,%7}, {%8,%9}, {%0,%1,%2,%3};"
                 : "+f"(c[0]), "+f"(c[1]), "+f"(c[2]), "+f"(c[3])
                 : "r"(a0), "r"(a1), "r"(a2), "r"(a3), "r"(b0), "r"(b1));
}

__device__ __forceinline__ float sigm(float x) { return 1.0f / (1.0f + __expf(-x)); }
__device__ __forceinline__ float tanh_fast(float x) { float e = __expf(2.0f * x); return 1.0f - 2.0f / (e + 1.0f); }

// ---------------- init kernel: zero g_h[0] ----------------
__global__ void init_kernel() {
    int i = blockIdx.x * blockDim.x + threadIdx.x;
    for (; i < BATCH * UNITS; i += gridDim.x * blockDim.x) g_h[0][i] = 0u;
}

// ---------------- main persistent kernel ----------------
__global__ void __launch_bounds__(NTHREADS, 1) __cluster_dims__(CPG, 1, 1)
lstm_kernel(const int* __restrict__ tokens,
            const float* __restrict__ Wx,
            const float* __restrict__ Wh,
            const float* __restrict__ bias,
            const float* __restrict__ Wd,
            const float* __restrict__ bd,
            float* __restrict__ out) {
    extern __shared__ __align__(1024) char smem[];
    const uint32_t sb = smem_u32(smem);
    const int tid = threadIdx.x;
    const int w   = tid >> 5;            // warp 0..15
    const int L   = tid & 31;
    const int mg  = w & 3;               // m-group (0..3): 32 m-rows
    const int nq  = w >> 2;              // n-quarter (0..3): 8 n-cols
    const int group = blockIdx.x >> 3;
    const int r     = blockIdx.x & 7;    // cluster rank
    const int gbase = group * MBATCH;

    float* wx_s = (float*)(smem + OFF_WX);

    // ---- prologue: W_h slice (fp32 -> bf16 hi/lo), Wx fp32 slice ----
    // A-row map per 32-row m-group: gate = rw>>3 (i,j,f,o), unit_local = mgrp*8 + (rw&7)
    {
        const int m  = tid & 127;
        const int kh = tid >> 7;                  // quarter 0..3
        const int rw = m & 31;
        const int gate = rw >> 3;
        const int ulocal = (m >> 5) * 8 + (rw & 7);
        const int col = gate * 256 + r * UC + ulocal;
        for (int k = kh * 64; k < kh * 64 + 64; k++) {
            float wv = Wh[k * 1024 + col];
            __nv_bfloat16 hi = __float2bfloat16(wv);
            float rem = wv - __bfloat162float(hi);
            __nv_bfloat16 lo = __float2bfloat16(rem);
            uint32_t s = swz(m, k);
            *(__nv_bfloat16*)(smem + OFF_AHI + s) = hi;
            *(__nv_bfloat16*)(smem + OFF_ALO + s) = lo;
        }
        for (int ch = kh * 32; ch < kh * 32 + 32; ch++)
            wx_s[(gate * 32 + ulocal) * 130 + ch] = Wx[ch * 1024 + col];
    }

    // per-lane owned unit + bias regs
    const int ul = mg * 8 + (L >> 2);            // unit local 0..31
    const float bi = bias[0 * 256 + r * UC + ul];
    const float bj = bias[1 * 256 + r * UC + ul];
    const float bf = bias[2 * 256 + r * UC + ul];
    const float bo = bias[3 * 256 + r * UC + ul];
    const float* wxi = &wx_s[(0 * 32 + ul) * 130];
    const float* wxj = &wx_s[(1 * 32 + ul) * 130];
    const float* wxf = &wx_s[(2 * 32 + ul) * 130];
    const float* wxo = &wx_s[(3 * 32 + ul) * 130];

    // ---- per-lane ldmatrix addresses ----
    // A (32m x 16k per k-step, two 16x16 tiles):
    const int rA   = (L & 7) + 8 * ((L >> 3) & 1);
    const uint32_t koffA = (L >> 4) ? 16u : 0u;     // bytes (8 elements)
    const int rowA0 = mg * 32 + rA;
    const int rowA1 = rowA0 + 16;
    const uint32_t xA = ((uint32_t)rowA0 & 7u) << 4;
    const uint32_t aHi0 = sb + OFF_AHI + rowA0 * 512u;
    const uint32_t aHi1 = sb + OFF_AHI + rowA1 * 512u;
    const uint32_t aLo0 = sb + OFF_ALO + rowA0 * 512u;
    const uint32_t aLo1 = sb + OFF_ALO + rowA1 * 512u;
    // B (8n x 16k per k-step, ldmatrix.x2: lanes 0-7 k+0 chunk, 8-15 k+8 chunk)
    const int L16 = L & 15;
    const int rB = L16 & 7;
    const uint32_t koffB = ((L16 >> 3) & 1) ? 16u : 0u;   // bytes
    const int nB = nq * 8 + rB;
    const uint32_t xB = ((uint32_t)rB & 7u) << 4;
    const uint32_t bHi = sb + OFF_BHI + nB * 512u;
    const uint32_t bLo = sb + OFF_BLO + nB * 512u;

    // per-lane batch columns: bb(j) = nq*8 + (L&3)*2 + j
    int bbs[2];
#pragma unroll
    for (int j = 0; j < 2; j++) bbs[j] = nq * 8 + (L & 3) * 2 + j;

    float c_reg[2] = {0.0f, 0.0f};

    __syncthreads();          // wx_s / A tiles written
    CLUSTER_ARRIVE();         // phase 0 (prologue done; init_kernel zeros already visible)

    // prefetch tokens + Wx gather for t=0 (runs in barrier-skew shadow)
    float wvi[2], wvj[2], wvf[2], wvo[2];
#pragma unroll
    for (int e = 0; e < 2; e++) {
        int tk = __ldg(&tokens[(gbase + bbs[e]) * SEQ + 0]);
        wvi[e] = wxi[tk]; wvj[e] = wxj[tk]; wvf[e] = wxf[tk]; wvo[e] = wxo[tk];
    }

    // ---- 1024 recurrent steps ----
    for (int t = 0; t < SEQ; t++) {
        CLUSTER_WAIT();   // all CTAs' h stores for step t visible; also CTA-wide barrier

        // load h (packed bf16 hi/lo), unpack into swizzled Bhi/Blo
        {
            const uint4* src = (const uint4*)&g_h[t & 1][gbase * UNITS];
#pragma unroll
            for (int ii = 0; ii < 4; ii++) {
                int idx4 = tid + (ii << 9);
                uint4 p = __ldcg(src + idx4);
                int n  = idx4 >> 6;
                int k4 = (idx4 & 63) << 2;
                uint32_t hi01 = (p.x & 0xFFFFu) | (p.y << 16);
                uint32_t hi23 = (p.z & 0xFFFFu) | (p.w << 16);
                uint32_t lo01 = (p.x >> 16) | (p.y & 0xFFFF0000u);
                uint32_t lo23 = (p.z >> 16) | (p.w & 0xFFFF0000u);
                uint32_t s = swz(n, k4);
                *(uint2*)(smem + OFF_BHI + s) = make_uint2(hi01, hi23);
                *(uint2*)(smem + OFF_BLO + s) = make_uint2(lo01, lo23);
            }
        }
        __syncthreads();

        // ---- MMA: gates[128,32] = Whi*hhi + Whi*hlo + Wlo*hhi over K=256 ----
        float acc[2][4];
#pragma unroll
        for (int mt = 0; mt < 2; mt++)
#pragma unroll
            for (int e = 0; e < 4; e++) acc[mt][e] = 0.0f;

#pragma unroll 4
        for (int ks = 0; ks < 16; ks++) {
            const uint32_t ka = ((uint32_t)(ks * 32) + koffA) ^ xA;
            const uint32_t kb = ((uint32_t)(ks * 32) + koffB) ^ xB;
            uint32_t Ah0[4], Ah1[4], Al0[4], Al1[4], Bh[2], Bl[2];
            ldsm_x4(Ah0, aHi0 + ka);
            ldsm_x4(Ah1, aHi1 + ka);
            ldsm_x4(Al0, aLo0 + ka);
            ldsm_x4(Al1, aLo1 + ka);
            ldsm_x2(Bh, bHi + kb);
            ldsm_x2(Bl, bLo + kb);
            mma_bf16(acc[0], Ah0[0], Ah0[1], Ah0[2], Ah0[3], Bh[0], Bh[1]);
            mma_bf16(acc[1], Ah1[0], Ah1[1], Ah1[2], Ah1[3], Bh[0], Bh[1]);
            mma_bf16(acc[0], Ah0[0], Ah0[1], Ah0[2], Ah0[3], Bl[0], Bl[1]);
            mma_bf16(acc[1], Ah1[0], Ah1[1], Ah1[2], Ah1[3], Bl[0], Bl[1]);
            mma_bf16(acc[0], Al0[0], Al0[1], Al0[2], Al0[3], Bh[0], Bh[1]);
            mma_bf16(acc[1], Al1[0], Al1[1], Al1[2], Al1[3], Bh[0], Bh[1]);
        }

        // ---- LSTM elementwise in registers (lane owns unit ul, 2 batch cols) ----
        // acc[0][j]=gate_i, acc[0][2+j]=gate_j, acc[1][j]=gate_f, acc[1][2+j]=gate_o
        {
            unsigned* dst = &g_h[(t + 1) & 1][0];
#pragma unroll
            for (int j = 0; j < 2; j++) {
                float gi = acc[0][j]     + wvi[j] + bi;
                float gj = acc[0][2 + j] + wvj[j] + bj;
                float gf = acc[1][j]     + wvf[j] + bf;
                float go = acc[1][2 + j] + wvo[j] + bo;
                float nc = c_reg[j] * sigm(gf + 1.0f) + sigm(gi) * tanh_fast(gj);
                c_reg[j] = nc;
                float nh2 = tanh_fast(nc) * sigm(go);
                __nv_bfloat16 hi = __float2bfloat16(nh2);
                float rem = nh2 - __bfloat162float(hi);
                __nv_bfloat16 lo = __float2bfloat16(rem);
                unsigned packed = (unsigned)__bfloat16_as_ushort(hi) | ((unsigned)__bfloat16_as_ushort(lo) << 16);
                __stcg(&dst[(gbase + bbs[j]) * UNITS + r * UC + ul], packed);
            }
        }
        CLUSTER_ARRIVE();   // my h(t+1) stores issued & ordered (release)

        // prefetch next step's tokens + Wx gather in the skew shadow
        {
            const int tp = (t + 1 < SEQ) ? (t + 1) : (SEQ - 1);
#pragma unroll
            for (int e = 0; e < 2; e++) {
                int tk = __ldg(&tokens[(gbase + bbs[e]) * SEQ + tp]);
                wvi[e] = wxi[tk]; wvj[e] = wxj[tk]; wvf[e] = wxf[tk]; wvo[e] = wxo[tk];
            }
        }
    }

    // ---- dense head: logits = h @ W_dense + b_dense (final h in g_h[0]) ----
    CLUSTER_WAIT();   // final h stores visible; CTA-wide barrier (safe to reuse AHI smem)
    {
        float* hs = (float*)(smem + OFF_AHI);   // reuse A region: 4 rows x 256 fp32
        const int bstart = r * 4;
        for (int i = tid; i < 4 * UNITS; i += NTHREADS) {
            unsigned p = __ldcg(&g_h[0][(gbase + bstart + (i >> 8)) * UNITS + (i & 255)]);
            hs[i] = __bfloat162float(__ushort_as_bfloat16((unsigned short)(p & 0xFFFFu))) +
                    __bfloat162float(__ushort_as_bfloat16((unsigned short)(p >> 16)));
        }
        __syncthreads();
        const int n   = tid & 127;   // output char
        const int row = tid >> 7;    // batch row 0..3
        float a0 = bd[n];
        for (int k = 0; k < UNITS; k++)
            a0 += hs[row * 256 + k] * Wd[k * NUM_CHARS + n];
        out[(gbase + bstart + row) * NUM_CHARS + n] = a0;
    }
}

// ---------------- host launcher ----------------
extern "C" void kernel_launch(void* const* d_in, const int* in_sizes, int n_in,
                              void* d_out, int out_size) {
    (void)in_sizes; (void)n_in; (void)out_size;
    const int*   tokens = (const int*)d_in[0];
    const float* Wx     = (const float*)d_in[1];
    const float* Wh     = (const float*)d_in[2];
    const float* b      = (const float*)d_in[3];
    const float* Wd     = (const float*)d_in[4];
    const float* bdn    = (const float*)d_in[5];
    float* out = (float*)d_out;

    cudaFuncSetAttribute(lstm_kernel, cudaFuncAttributeMaxDynamicSharedMemorySize, SMEM_TOTAL);

    init_kernel<<<256, 256>>>();
    lstm_kernel<<<NCTAS, NTHREADS, SMEM_TOTAL>>>(tokens, Wx, Wh, b, Wd, bdn, out);
}